// round 8
// baseline (speedup 1.0000x reference)
#include <cuda_runtime.h>
#include <cuda_fp16.h>

// Inputs (metadata order):
//  0 embed  [N,64] f32          (N=1500)
//  1 edge_index [2,E]           (E=65536; int32 OR int64, per-warp sniffed)
//  2 noise  [N*N] f32
//  3 tmp    [1] f32  (temperature beta)
//  4 W1     [128,64] f32
//  5 b1     [64] f32
//  6 W2     [64,1] f32
//  7 b2     [1] f32
// Output: edge_mask [E] f32
//
// Single fused kernel: blocks [0,P) produce the per-node hidden table g_h16,
// blocks [P,P+Q) each handle 64 edges. Edge blocks decode indices + issue
// their scattered noise loads BEFORE spinning on the producer counter, so the
// longest-latency loads overlap the producer phase.

#define MAXN 1500

// Per node n, row of 128 halfs: [0:64) = h1[n]+b1, [64:128) = h2[n]  (384 KB)
__device__ __align__(256) __half g_h16[MAXN * 128];
__device__ int g_done = 0;   // producer blocks finished
__device__ int g_fin  = 0;   // edge blocks finished (for self-reset)

// 8 halfs (one uint4 of fp16 h) -> relu(a+c) dot W2[8]
__device__ __forceinline__ float dot8(uint4 a, uint4 c, float4 wa, float4 wb)
{
    const __half2* ah = (const __half2*)&a;
    const __half2* ch = (const __half2*)&c;
    const __half2  z  = __float2half2_rn(0.0f);
    float2 f0 = __half22float2(__hmax2(__hadd2(ah[0], ch[0]), z));
    float2 f1 = __half22float2(__hmax2(__hadd2(ah[1], ch[1]), z));
    float2 f2 = __half22float2(__hmax2(__hadd2(ah[2], ch[2]), z));
    float2 f3 = __half22float2(__hmax2(__hadd2(ah[3], ch[3]), z));
    float s = f0.x * wa.x;
    s = fmaf(f0.y, wa.y, s);
    s = fmaf(f1.x, wa.z, s);
    s = fmaf(f1.y, wa.w, s);
    s = fmaf(f2.x, wb.x, s);
    s = fmaf(f2.y, wb.y, s);
    s = fmaf(f3.x, wb.z, s);
    s = fmaf(f3.y, wb.w, s);
    return s;
}

__global__ void __launch_bounds__(256) fused(
    const float* __restrict__ embed,
    const void*  __restrict__ ei_raw,
    const float* __restrict__ noise,
    const float* __restrict__ tmpp,
    const float* __restrict__ W1,
    const float* __restrict__ b1,
    const float* __restrict__ W2,
    const float* __restrict__ b2,
    float* __restrict__ out,
    int N, int E, int P, int Q)
{
    int t    = threadIdx.x;
    int lane = t & 31;
    int wid  = t >> 5;

    if ((int)blockIdx.x < P) {
        // ---------------- producer: 8 nodes per block ----------------
        __shared__ float se[8 * 64];
        int n0 = blockIdx.x * 8;
#pragma unroll
        for (int idx = t; idx < 512; idx += 256) {
            int nl = idx >> 6, f = idx & 63;
            se[idx] = (n0 + nl < N) ? embed[(n0 + nl) * 64 + f] : 0.0f;
        }
        __syncthreads();

        int nl   = t >> 5;            // node-local 0..7 (one warp per node)
        int half = (t >> 4) & 1;      // 0 -> h1, 1 -> h2
        int k0   = (t & 15) * 4;      // 4 adjacent k
        int node = n0 + nl;

        const float* es = se + nl * 64;
        float4 s = make_float4(0.f, 0.f, 0.f, 0.f);
#pragma unroll
        for (int f = 0; f < 64; f++) {
            float e = es[f];
            float4 w = *(const float4*)&W1[(half * 64 + f) * 64 + k0];
            s.x = fmaf(e, w.x, s.x);
            s.y = fmaf(e, w.y, s.y);
            s.z = fmaf(e, w.z, s.z);
            s.w = fmaf(e, w.w, s.w);
        }
        if (half == 0) {
            s.x += b1[k0];     s.y += b1[k0 + 1];
            s.z += b1[k0 + 2]; s.w += b1[k0 + 3];
        }
        if (node < N) {
            __half2 lo = __floats2half2_rn(s.x, s.y);
            __half2 hi = __floats2half2_rn(s.z, s.w);
            uint2 pack;
            pack.x = *(unsigned*)&lo;
            pack.y = *(unsigned*)&hi;
            *(uint2*)&g_h16[node * 128 + half * 64 + k0] = pack;
        }
        __syncthreads();
        if (t == 0) {
            __threadfence();
            atomicAdd(&g_done, 1);
        }
        return;
    }

    // ---------------- consumer: 8 edges per warp, 64 per block ----------------
    int gwarp = (blockIdx.x - P) * 8 + wid;
    int base  = gwarp * 8;            // first edge of this warp

    int el  = lane >> 2;              // edge-local 0..7
    int m   = lane & 1;               // half of the 64-dot (32 k's)
    int top = (lane >> 1) & 1;        // 0: (i,j), 1: (j,i)

    const int* w32 = (const int*)ei_raw;
    int k8 = lane & 7;
    int ek = min(base + k8, E - 1);

    // dtype sniff: for genuine int64 src values the odd words are all zero.
    int ow = (lane < 8) ? w32[2 * ek + 1] : 0;
    bool is64 = (__ballot_sync(0xffffffffu, ow != 0) == 0u);

    // index loads: lanes 0-7 src, lanes 8-15 dst
    int val = 0;
    if (lane < 16) {
        if (is64) val = (lane < 8) ? w32[2 * ek] : w32[2 * E + 2 * ek];
        else      val = (lane < 8) ? w32[ek]     : w32[E + ek];
    }
    int i = __shfl_sync(0xffffffffu, val, el);
    int j = __shfl_sync(0xffffffffu, val, 8 + el);
    i = min(max(i, 0), N - 1);
    j = min(max(j, 0), N - 1);

    // scattered noise load issued BEFORE the spin -> overlaps producer phase
    float nz = 0.0f;
    if (m == 0) nz = __ldg(noise + (top ? (j * N + i) : (i * N + j)));

    // wait for the producer table
    if (lane == 0) {
        while (*(volatile int*)&g_done < P) __nanosleep(32);
    }
    __syncwarp();
    __threadfence();   // acquire: order g_h16 reads after the flag

    const uint4* A4 = (const uint4*)(g_h16 + (top ? j : i) * 128) + m * 4;       // h1
    const uint4* B4 = (const uint4*)(g_h16 + (top ? i : j) * 128 + 64) + m * 4;  // h2
    const float4* W = (const float4*)W2 + m * 8;

    uint4 a0 = A4[0], a1 = A4[1], a2 = A4[2], a3 = A4[3];
    uint4 c0 = B4[0], c1 = B4[1], c2 = B4[2], c3 = B4[3];

    float s = dot8(a0, c0, W[0], W[1])
            + dot8(a1, c1, W[2], W[3])
            + dot8(a2, c2, W[4], W[5])
            + dot8(a3, c3, W[6], W[7]);

    // reduce the two lanes of this direction
    s += __shfl_xor_sync(0xffffffffu, s, 1);

    // gate on m==0 lanes (16 lanes: all 16 directions in one MUFU pass)
    float g = 0.0f;
    if (m == 0) {
        float inv_beta = 1.0f / tmpp[0];
        float x = (__logf(nz) - __logf(1.0f - nz) + s + b2[0]) * inv_beta;
        g = 1.0f / (1.0f + __expf(-x));
    }
    // combine directions: lane 4el <- lane 4el+2
    float go = __shfl_xor_sync(0xffffffffu, g, 2);
    int e = base + el;
    if ((lane & 3) == 0 && e < E)
        out[e] = 0.5f * (g + go);

    // self-reset of the counters for the next graph replay
    __syncthreads();
    if (t == 0) {
        int f = atomicAdd(&g_fin, 1);
        if (f == Q - 1) {
            *(volatile int*)&g_done = 0;
            __threadfence();
            *(volatile int*)&g_fin = 0;
        }
    }
}

// ---------------------------------------------------------------------------
extern "C" void kernel_launch(void* const* d_in, const int* in_sizes, int n_in,
                              void* d_out, int out_size)
{
    const float* embed = (const float*)d_in[0];
    const void*  ei    = d_in[1];
    const float* noise = (const float*)d_in[2];
    const float* tmp   = (const float*)d_in[3];
    const float* W1    = (const float*)d_in[4];
    const float* b1    = (const float*)d_in[5];
    const float* W2    = (const float*)d_in[6];
    const float* b2    = (const float*)d_in[7];
    float*       out   = (float*)d_out;

    int N = in_sizes[0] / 64;      // 1500
    int E = in_sizes[1] / 2;       // 65536

    int P = (N + 7) / 8;           // producer blocks (8 nodes each)
    int Q = (E + 63) / 64;         // edge blocks (64 edges each)

    fused<<<P + Q, 256>>>(embed, ei, noise, tmp, W1, b1, W2, b2,
                          out, N, E, P, Q);
}

// round 9
// speedup vs baseline: 1.5777x; 1.5777x over previous
#include <cuda_runtime.h>
#include <cuda_fp16.h>

// Inputs (metadata order):
//  0 embed  [N,64] f32          (N=1500)
//  1 edge_index [2,E]           (E=65536; int32 OR int64, per-warp sniffed)
//  2 noise  [N*N] f32
//  3 tmp    [1] f32  (temperature beta)
//  4 W1     [128,64] f32
//  5 b1     [64] f32
//  6 W2     [64,1] f32
//  7 b2     [1] f32
// Output: edge_mask [E] f32

#define MAXN 1500

// Per node n, row of 128 halfs: [0:64) = h1[n]+b1, [64:128) = h2[n]  (384 KB)
__device__ __align__(256) __half g_h16[MAXN * 128];

// ---------------------------------------------------------------------------
// Kernel 1: h1 = embed @ W1[:64] + b1 ; h2 = embed @ W1[64:]  (stored fp16)
// 8 nodes per block (one warp per node), float4 W1 rows, coalesced.
// ---------------------------------------------------------------------------
__global__ void __launch_bounds__(256) precompute_h(
    const float* __restrict__ embed,
    const float* __restrict__ W1,
    const float* __restrict__ b1,
    int N)
{
    __shared__ float se[8 * 64];
    int t  = threadIdx.x;
    int n0 = blockIdx.x * 8;

#pragma unroll
    for (int idx = t; idx < 512; idx += 256) {
        int nl = idx >> 6, f = idx & 63;
        se[idx] = (n0 + nl < N) ? embed[(n0 + nl) * 64 + f] : 0.0f;
    }
    __syncthreads();

    int nl   = t >> 5;            // node-local 0..7 (one warp per node)
    int half = (t >> 4) & 1;      // 0 -> h1, 1 -> h2
    int k0   = (t & 15) * 4;      // 4 adjacent k
    int node = n0 + nl;

    const float* es = se + nl * 64;
    float4 s = make_float4(0.f, 0.f, 0.f, 0.f);
#pragma unroll
    for (int f = 0; f < 64; f++) {
        float e = es[f];
        float4 w = *(const float4*)&W1[(half * 64 + f) * 64 + k0];
        s.x = fmaf(e, w.x, s.x);
        s.y = fmaf(e, w.y, s.y);
        s.z = fmaf(e, w.z, s.z);
        s.w = fmaf(e, w.w, s.w);
    }
    if (half == 0) {
        s.x += b1[k0];     s.y += b1[k0 + 1];
        s.z += b1[k0 + 2]; s.w += b1[k0 + 3];
    }
    if (node < N) {
        __half2 lo = __floats2half2_rn(s.x, s.y);
        __half2 hi = __floats2half2_rn(s.z, s.w);
        uint2 pack;
        pack.x = *(unsigned*)&lo;
        pack.y = *(unsigned*)&hi;
        *(uint2*)&g_h16[node * 128 + half * 64 + k0] = pack;
    }
}

// 8 halfs (one uint4 of fp16 h) -> relu(a+c) dot W2[8]
__device__ __forceinline__ float dot8(uint4 a, uint4 c, float4 wa, float4 wb)
{
    const __half2* ah = (const __half2*)&a;
    const __half2* ch = (const __half2*)&c;
    const __half2  z  = __float2half2_rn(0.0f);
    float2 f0 = __half22float2(__hmax2(__hadd2(ah[0], ch[0]), z));
    float2 f1 = __half22float2(__hmax2(__hadd2(ah[1], ch[1]), z));
    float2 f2 = __half22float2(__hmax2(__hadd2(ah[2], ch[2]), z));
    float2 f3 = __half22float2(__hmax2(__hadd2(ah[3], ch[3]), z));
    float s = f0.x * wa.x;
    s = fmaf(f0.y, wa.y, s);
    s = fmaf(f1.x, wa.z, s);
    s = fmaf(f1.y, wa.w, s);
    s = fmaf(f2.x, wb.x, s);
    s = fmaf(f2.y, wb.y, s);
    s = fmaf(f3.x, wb.z, s);
    s = fmaf(f3.y, wb.w, s);
    return s;
}

// ---------------------------------------------------------------------------
// Kernel 2: 8 edges per warp, no block barriers.
//   lane layout: el = lane>>2 (edge 0..7), top = (lane>>1)&1 (direction),
//   m = lane&1 (32-k half of the dot). Per-warp dtype sniff via ballot.
//   Each lane: 4+4 uint4 fp16 h loads (independent), fp32 fma vs W2.
// ---------------------------------------------------------------------------
__global__ void __launch_bounds__(256) edge_gate(
    const void* __restrict__ ei_raw,
    const float* __restrict__ noise,
    const float* __restrict__ tmpp,
    const float* __restrict__ W2,
    const float* __restrict__ b2,
    float* __restrict__ out,
    int N, int E)
{
    int tid   = threadIdx.x;
    int lane  = tid & 31;
    int gwarp = (blockIdx.x * blockDim.x + tid) >> 5;
    int base  = gwarp * 8;            // first edge of this warp

    int el  = lane >> 2;              // edge-local 0..7
    int m   = lane & 1;               // half of the 64-dot (32 k's)
    int top = (lane >> 1) & 1;        // 0: (i,j), 1: (j,i)

    const int* w32 = (const int*)ei_raw;
    int k8 = lane & 7;
    int ek = min(base + k8, E - 1);

    // dtype sniff: genuine int64 src values < 2^31 -> odd words all zero.
    int ow = (lane < 8) ? w32[2 * ek + 1] : 0;
    bool is64 = (__ballot_sync(0xffffffffu, ow != 0) == 0u);

    // index loads: lanes 0-7 src, lanes 8-15 dst
    int val = 0;
    if (lane < 16) {
        if (is64) val = (lane < 8) ? w32[2 * ek] : w32[2 * E + 2 * ek];
        else      val = (lane < 8) ? w32[ek]     : w32[E + ek];
    }
    int i = __shfl_sync(0xffffffffu, val, el);
    int j = __shfl_sync(0xffffffffu, val, 8 + el);
    i = min(max(i, 0), N - 1);
    j = min(max(j, 0), N - 1);

    // scattered noise load (DRAM) issued early, one per direction (16 lanes)
    float nz = 0.0f;
    if (m == 0) nz = __ldg(noise + (top ? (j * N + i) : (i * N + j)));

    const uint4* A4 = (const uint4*)(g_h16 + (top ? j : i) * 128) + m * 4;       // h1
    const uint4* B4 = (const uint4*)(g_h16 + (top ? i : j) * 128 + 64) + m * 4;  // h2
    const float4* W = (const float4*)W2 + m * 8;

    uint4 a0 = A4[0], a1 = A4[1], a2 = A4[2], a3 = A4[3];
    uint4 c0 = B4[0], c1 = B4[1], c2 = B4[2], c3 = B4[3];

    float s = dot8(a0, c0, W[0], W[1])
            + dot8(a1, c1, W[2], W[3])
            + dot8(a2, c2, W[4], W[5])
            + dot8(a3, c3, W[6], W[7]);

    // reduce the two lanes of this direction
    s += __shfl_xor_sync(0xffffffffu, s, 1);

    // gate on m==0 lanes (16 lanes: all 16 directions in one MUFU pass)
    float g = 0.0f;
    if (m == 0) {
        float inv_beta = 1.0f / tmpp[0];
        float x = (__logf(nz) - __logf(1.0f - nz) + s + b2[0]) * inv_beta;
        g = 1.0f / (1.0f + __expf(-x));
    }
    // combine directions: lane 4el <- lane 4el+2
    float go = __shfl_xor_sync(0xffffffffu, g, 2);
    int e = base + el;
    if ((lane & 3) == 0 && e < E)
        out[e] = 0.5f * (g + go);
}

// ---------------------------------------------------------------------------
extern "C" void kernel_launch(void* const* d_in, const int* in_sizes, int n_in,
                              void* d_out, int out_size)
{
    const float* embed = (const float*)d_in[0];
    const void*  ei    = d_in[1];
    const float* noise = (const float*)d_in[2];
    const float* tmp   = (const float*)d_in[3];
    const float* W1    = (const float*)d_in[4];
    const float* b1    = (const float*)d_in[5];
    const float* W2    = (const float*)d_in[6];
    const float* b2    = (const float*)d_in[7];
    float*       out   = (float*)d_out;

    int N = in_sizes[0] / 64;      // 1500
    int E = in_sizes[1] / 2;       // 65536

    precompute_h<<<(N + 7) / 8, 256>>>(embed, W1, b1, N);

    // 8 edges per warp, 8 warps per block -> 64 edges per block
    int blocks = (E + 63) / 64;
    edge_gate<<<blocks, 256>>>(ei, noise, tmp, W2, b2, out, N, E);
}

// round 10
// speedup vs baseline: 1.6270x; 1.0313x over previous
#include <cuda_runtime.h>
#include <cuda_fp16.h>

// Inputs (metadata order):
//  0 embed  [N,64] f32          (N=1500)
//  1 edge_index [2,E]           (E=65536; int32 OR int64, per-warp sniffed)
//  2 noise  [N*N] f32
//  3 tmp    [1] f32
//  4 W1     [128,64] f32
//  5 b1     [64] f32
//  6 W2     [64,1] f32
//  7 b2     [1] f32
// Output: edge_mask [E] f32

#define MAXN 1500

// Per node n, row of 128 halfs: [0:64) = h1[n]+b1, [64:128) = h2[n]  (384 KB)
__device__ __align__(256) __half g_h16[MAXN * 128];

// ---------------------------------------------------------------------------
// Kernel 1: h table (fp16). 16 nodes per block, 2 nodes per thread:
// each W1 float4 load feeds 8 FMAs -> half the LDG count per output.
// ---------------------------------------------------------------------------
__global__ void __launch_bounds__(256) precompute_h(
    const float* __restrict__ embed,
    const float* __restrict__ W1,
    const float* __restrict__ b1,
    int N)
{
    __shared__ float se[16 * 64];
    int t  = threadIdx.x;
    int n0 = blockIdx.x * 16;

#pragma unroll
    for (int idx = t; idx < 1024; idx += 256) {
        int nl = idx >> 6, f = idx & 63;
        se[idx] = (n0 + nl < N) ? embed[(n0 + nl) * 64 + f] : 0.0f;
    }
    __syncthreads();

    int slot = t & 31;            // which (half, k-quad)
    int half = slot >> 4;         // 0 -> h1, 1 -> h2
    int k0   = (slot & 15) * 4;   // 4 adjacent k
    int grp  = t >> 5;            // 0..7 -> nodes grp and grp+8

    const float* e0 = se + grp * 64;
    const float* e1 = se + (grp + 8) * 64;

    float4 s0 = make_float4(0.f, 0.f, 0.f, 0.f);
    float4 s1 = make_float4(0.f, 0.f, 0.f, 0.f);
#pragma unroll
    for (int f = 0; f < 64; f++) {
        float4 w = *(const float4*)&W1[(half * 64 + f) * 64 + k0];
        float a = e0[f], b = e1[f];
        s0.x = fmaf(a, w.x, s0.x); s0.y = fmaf(a, w.y, s0.y);
        s0.z = fmaf(a, w.z, s0.z); s0.w = fmaf(a, w.w, s0.w);
        s1.x = fmaf(b, w.x, s1.x); s1.y = fmaf(b, w.y, s1.y);
        s1.z = fmaf(b, w.z, s1.z); s1.w = fmaf(b, w.w, s1.w);
    }
    if (half == 0) {
        float4 bb = *(const float4*)&b1[k0];
        s0.x += bb.x; s0.y += bb.y; s0.z += bb.z; s0.w += bb.w;
        s1.x += bb.x; s1.y += bb.y; s1.z += bb.z; s1.w += bb.w;
    }

    int node0 = n0 + grp, node1 = n0 + grp + 8;
    if (node0 < N) {
        __half2 lo = __floats2half2_rn(s0.x, s0.y);
        __half2 hi = __floats2half2_rn(s0.z, s0.w);
        uint2 p; p.x = *(unsigned*)&lo; p.y = *(unsigned*)&hi;
        *(uint2*)&g_h16[node0 * 128 + half * 64 + k0] = p;
    }
    if (node1 < N) {
        __half2 lo = __floats2half2_rn(s1.x, s1.y);
        __half2 hi = __floats2half2_rn(s1.z, s1.w);
        uint2 p; p.x = *(unsigned*)&lo; p.y = *(unsigned*)&hi;
        *(uint2*)&g_h16[node1 * 128 + half * 64 + k0] = p;
    }
}

// 8 halfs (one uint4 of fp16 h) -> relu(a+c) dot W2[8]
__device__ __forceinline__ float dot8(uint4 a, uint4 c, float4 wa, float4 wb)
{
    const __half2* ah = (const __half2*)&a;
    const __half2* ch = (const __half2*)&c;
    const __half2  z  = __float2half2_rn(0.0f);
    float2 f0 = __half22float2(__hmax2(__hadd2(ah[0], ch[0]), z));
    float2 f1 = __half22float2(__hmax2(__hadd2(ah[1], ch[1]), z));
    float2 f2 = __half22float2(__hmax2(__hadd2(ah[2], ch[2]), z));
    float2 f3 = __half22float2(__hmax2(__hadd2(ah[3], ch[3]), z));
    float s = f0.x * wa.x;
    s = fmaf(f0.y, wa.y, s);
    s = fmaf(f1.x, wa.z, s);
    s = fmaf(f1.y, wa.w, s);
    s = fmaf(f2.x, wb.x, s);
    s = fmaf(f2.y, wb.y, s);
    s = fmaf(f3.x, wb.z, s);
    s = fmaf(f3.y, wb.w, s);
    return s;
}

// ---------------------------------------------------------------------------
// Kernel 2: 2 edges per warp, 8 lanes per direction.
//   grp = lane>>3 (direction 0..3 = 2 edges x 2 dirs), m = lane&7.
//   Each lane: ONE uint4 of h1 + ONE of h2; 8 lanes cover the full 128B row
//   -> each h-LDG touches only 4 cache lines (minimal L1 wavefronts).
// ---------------------------------------------------------------------------
__global__ void __launch_bounds__(256) edge_gate(
    const void* __restrict__ ei_raw,
    const float* __restrict__ noise,
    const float* __restrict__ tmpp,
    const float* __restrict__ W2,
    const float* __restrict__ b2,
    float* __restrict__ out,
    int N, int E)
{
    int tid   = threadIdx.x;
    int lane  = tid & 31;
    int gwarp = (blockIdx.x * blockDim.x + tid) >> 5;
    int base  = gwarp * 2;            // first edge of this warp

    int grp = lane >> 3;              // direction 0..3
    int m   = lane & 7;               // eighth of the 64-dot (8 k's)
    int el  = grp >> 1;               // edge-local 0..1
    int top = grp & 1;                // 0: (i,j), 1: (j,i)

    const int* w32 = (const int*)ei_raw;
    int ek = min(base + (lane & 1), E - 1);

    // dtype sniff: genuine int64 src values < 2^31 -> odd words all zero.
    int ow = (lane < 2) ? w32[2 * ek + 1] : 0;
    bool is64 = (__ballot_sync(0xffffffffu, ow != 0) == 0u);

    // index loads: lanes 0-1 src, lanes 2-3 dst
    int val = 0;
    if (lane < 4) {
        int ee = min(base + (lane & 1), E - 1);
        if (is64) val = (lane < 2) ? w32[2 * ee] : w32[2 * E + 2 * ee];
        else      val = (lane < 2) ? w32[ee]     : w32[E + ee];
    }
    int i = __shfl_sync(0xffffffffu, val, el);
    int j = __shfl_sync(0xffffffffu, val, 2 + el);
    i = min(max(i, 0), N - 1);
    j = min(max(j, 0), N - 1);

    // scattered noise load, one per direction (4 lanes), issued early
    float nz = 0.0f;
    if (m == 0) nz = __ldg(noise + (top ? (j * N + i) : (i * N + j)));

    // h1 of first node, h2 of second node of this direction
    const uint4* A = (const uint4*)(g_h16 + (top ? j : i) * 128) + m;      // h1
    const uint4* B = (const uint4*)(g_h16 + (top ? i : j) * 128) + 8 + m;  // h2
    uint4 a = A[0];
    uint4 c = B[0];

    const float4* W = (const float4*)W2 + 2 * m;
    float s = dot8(a, c, W[0], W[1]);

    // reduce across the 8 lanes of this direction
    s += __shfl_xor_sync(0xffffffffu, s, 1);
    s += __shfl_xor_sync(0xffffffffu, s, 2);
    s += __shfl_xor_sync(0xffffffffu, s, 4);

    // gate on m==0 lanes (4 lanes: all 4 directions in one MUFU pass)
    float g = 0.0f;
    if (m == 0) {
        float inv_beta = 1.0f / tmpp[0];
        float x = (__logf(nz) - __logf(1.0f - nz) + s + b2[0]) * inv_beta;
        g = 1.0f / (1.0f + __expf(-x));
    }
    // combine the two directions of each edge: lane 16el <- lane 16el+8
    float go = __shfl_xor_sync(0xffffffffu, g, 8);
    int e = base + el;
    if ((lane & 15) == 0 && e < E)
        out[e] = 0.5f * (g + go);
}

// ---------------------------------------------------------------------------
extern "C" void kernel_launch(void* const* d_in, const int* in_sizes, int n_in,
                              void* d_out, int out_size)
{
    const float* embed = (const float*)d_in[0];
    const void*  ei    = d_in[1];
    const float* noise = (const float*)d_in[2];
    const float* tmp   = (const float*)d_in[3];
    const float* W1    = (const float*)d_in[4];
    const float* b1    = (const float*)d_in[5];
    const float* W2    = (const float*)d_in[6];
    const float* b2    = (const float*)d_in[7];
    float*       out   = (float*)d_out;

    int N = in_sizes[0] / 64;      // 1500
    int E = in_sizes[1] / 2;       // 65536

    precompute_h<<<(N + 15) / 16, 256>>>(embed, W1, b1, N);

    // 2 edges per warp, 8 warps per block -> 16 edges per block
    int blocks = (E + 15) / 16;
    edge_gate<<<blocks, 256>>>(ei, noise, tmp, W2, b2, out, N, E);
}

// round 11
// speedup vs baseline: 1.6398x; 1.0079x over previous
#include <cuda_runtime.h>
#include <cuda_fp16.h>

// Inputs (metadata order):
//  0 embed  [N,64] f32          (N=1500)
//  1 edge_index [2,E]           (E=65536; int32 OR int64, per-warp sniffed)
//  2 noise  [N*N] f32
//  3 tmp    [1] f32
//  4 W1     [128,64] f32
//  5 b1     [64] f32
//  6 W2     [64,1] f32
//  7 b2     [1] f32
// Output: edge_mask [E] f32

#define MAXN 1500

// Per node n, row of 128 halfs: [0:64) = h1[n]+b1, [64:128) = h2[n]  (384 KB)
__device__ __align__(256) __half g_h16[MAXN * 128];

// ---------------------------------------------------------------------------
// Kernel 1: h table (fp16). 16 nodes per block, 2 nodes per thread.
// ---------------------------------------------------------------------------
__global__ void __launch_bounds__(256) precompute_h(
    const float* __restrict__ embed,
    const float* __restrict__ W1,
    const float* __restrict__ b1,
    int N)
{
    __shared__ float se[16 * 64];
    int t  = threadIdx.x;
    int n0 = blockIdx.x * 16;

#pragma unroll
    for (int idx = t; idx < 1024; idx += 256) {
        int nl = idx >> 6, f = idx & 63;
        se[idx] = (n0 + nl < N) ? embed[(n0 + nl) * 64 + f] : 0.0f;
    }
    __syncthreads();

    int slot = t & 31;            // which (half, k-quad)
    int half = slot >> 4;         // 0 -> h1, 1 -> h2
    int k0   = (slot & 15) * 4;   // 4 adjacent k
    int grp  = t >> 5;            // 0..7 -> nodes grp and grp+8

    const float* e0 = se + grp * 64;
    const float* e1 = se + (grp + 8) * 64;

    float4 s0 = make_float4(0.f, 0.f, 0.f, 0.f);
    float4 s1 = make_float4(0.f, 0.f, 0.f, 0.f);
#pragma unroll
    for (int f = 0; f < 64; f++) {
        float4 w = *(const float4*)&W1[(half * 64 + f) * 64 + k0];
        float a = e0[f], b = e1[f];
        s0.x = fmaf(a, w.x, s0.x); s0.y = fmaf(a, w.y, s0.y);
        s0.z = fmaf(a, w.z, s0.z); s0.w = fmaf(a, w.w, s0.w);
        s1.x = fmaf(b, w.x, s1.x); s1.y = fmaf(b, w.y, s1.y);
        s1.z = fmaf(b, w.z, s1.z); s1.w = fmaf(b, w.w, s1.w);
    }
    if (half == 0) {
        float4 bb = *(const float4*)&b1[k0];
        s0.x += bb.x; s0.y += bb.y; s0.z += bb.z; s0.w += bb.w;
        s1.x += bb.x; s1.y += bb.y; s1.z += bb.z; s1.w += bb.w;
    }

    int node0 = n0 + grp, node1 = n0 + grp + 8;
    if (node0 < N) {
        __half2 lo = __floats2half2_rn(s0.x, s0.y);
        __half2 hi = __floats2half2_rn(s0.z, s0.w);
        uint2 p; p.x = *(unsigned*)&lo; p.y = *(unsigned*)&hi;
        *(uint2*)&g_h16[node0 * 128 + half * 64 + k0] = p;
    }
    if (node1 < N) {
        __half2 lo = __floats2half2_rn(s1.x, s1.y);
        __half2 hi = __floats2half2_rn(s1.z, s1.w);
        uint2 p; p.x = *(unsigned*)&lo; p.y = *(unsigned*)&hi;
        *(uint2*)&g_h16[node1 * 128 + half * 64 + k0] = p;
    }
}

// 8 halfs (one uint4 of fp16 h) -> relu(a+c) dot W2[8]
__device__ __forceinline__ float dot8(uint4 a, uint4 c, float4 wa, float4 wb)
{
    const __half2* ah = (const __half2*)&a;
    const __half2* ch = (const __half2*)&c;
    const __half2  z  = __float2half2_rn(0.0f);
    float2 f0 = __half22float2(__hmax2(__hadd2(ah[0], ch[0]), z));
    float2 f1 = __half22float2(__hmax2(__hadd2(ah[1], ch[1]), z));
    float2 f2 = __half22float2(__hmax2(__hadd2(ah[2], ch[2]), z));
    float2 f3 = __half22float2(__hmax2(__hadd2(ah[3], ch[3]), z));
    float s = f0.x * wa.x;
    s = fmaf(f0.y, wa.y, s);
    s = fmaf(f1.x, wa.z, s);
    s = fmaf(f1.y, wa.w, s);
    s = fmaf(f2.x, wb.x, s);
    s = fmaf(f2.y, wb.y, s);
    s = fmaf(f3.x, wb.z, s);
    s = fmaf(f3.y, wb.w, s);
    return s;
}

// ---------------------------------------------------------------------------
// Kernel 2: 4 edges per warp = 2 software-pipelined batches of the
// 8-lanes-per-row layout. All loads (speculative dual-dtype index read,
// noise, h rows for BOTH batches) are issued before any consumption.
//   grp = lane>>3 (direction 0..3 of a batch), m = lane&7 (8 k's),
//   el = grp>>1 (edge-in-batch), top = grp&1.
// ---------------------------------------------------------------------------
__global__ void __launch_bounds__(256) edge_gate(
    const void* __restrict__ ei_raw,
    const float* __restrict__ noise,
    const float* __restrict__ tmpp,
    const float* __restrict__ W2,
    const float* __restrict__ b2,
    float* __restrict__ out,
    int N, int E)
{
    int tid   = threadIdx.x;
    int lane  = tid & 31;
    int gwarp = (blockIdx.x * blockDim.x + tid) >> 5;
    int base  = gwarp * 4;            // 4 edges per warp

    int grp = lane >> 3;              // direction 0..3 (within a batch)
    int m   = lane & 7;               // eighth of the 64-dot
    int el  = grp >> 1;               // edge-in-batch 0..1
    int top = grp & 1;                // 0: (i,j), 1: (j,i)

    const int* w32 = (const int*)ei_raw;

    // Speculative index fetch, both dtype interpretations, + sniff words.
    //  lanes 0-3 : src int32, edges base..base+3
    //  lanes 4-7 : dst int32
    //  lanes 8-11: src int64 (low word)     lanes 12-15: dst int64
    //  lanes 16-19: src odd words (sniff)
    int q  = lane & 7;
    int eq = min(base + (q & 3), E - 1);
    int v = 0;
    if (lane < 8)        v = (q < 4) ? w32[eq] : w32[E + eq];
    else if (lane < 16)  v = (q < 4) ? w32[2 * eq] : w32[2 * E + 2 * eq];
    else if (lane < 20)  v = w32[2 * eq + 1];

    bool is64 = ((__ballot_sync(0xffffffffu, v != 0) & 0x000F0000u) == 0u);
    int sb = is64 ? 8 : 0;

    // batch 0 = edges base+0,base+1 ; batch 1 = edges base+2,base+3
    int i0 = __shfl_sync(0xffffffffu, v, sb + el);
    int j0 = __shfl_sync(0xffffffffu, v, sb + 4 + el);
    int i1 = __shfl_sync(0xffffffffu, v, sb + 2 + el);
    int j1 = __shfl_sync(0xffffffffu, v, sb + 6 + el);
    i0 = min(max(i0, 0), N - 1);  j0 = min(max(j0, 0), N - 1);
    i1 = min(max(i1, 0), N - 1);  j1 = min(max(j1, 0), N - 1);

    // scattered noise loads for both batches (m==0 lanes: 4 per warp, 2 each)
    float nz0 = 0.0f, nz1 = 0.0f;
    if (m == 0) {
        nz0 = __ldg(noise + (top ? (j0 * N + i0) : (i0 * N + j0)));
        nz1 = __ldg(noise + (top ? (j1 * N + i1) : (i1 * N + j1)));
    }

    // h rows for both batches: 4 independent LDG.128, minimal wavefronts
    const uint4* A0 = (const uint4*)(g_h16 + (top ? j0 : i0) * 128) + m;
    const uint4* B0 = (const uint4*)(g_h16 + (top ? i0 : j0) * 128) + 8 + m;
    const uint4* A1 = (const uint4*)(g_h16 + (top ? j1 : i1) * 128) + m;
    const uint4* B1 = (const uint4*)(g_h16 + (top ? i1 : j1) * 128) + 8 + m;
    uint4 a0 = __ldg(A0);
    uint4 c0 = __ldg(B0);
    uint4 a1 = __ldg(A1);
    uint4 c1 = __ldg(B1);

    const float4* W = (const float4*)W2 + 2 * m;
    float4 wa = W[0], wb = W[1];

    float s0 = dot8(a0, c0, wa, wb);
    float s1 = dot8(a1, c1, wa, wb);

    // interleaved reduces (two independent chains)
    s0 += __shfl_xor_sync(0xffffffffu, s0, 1);
    s1 += __shfl_xor_sync(0xffffffffu, s1, 1);
    s0 += __shfl_xor_sync(0xffffffffu, s0, 2);
    s1 += __shfl_xor_sync(0xffffffffu, s1, 2);
    s0 += __shfl_xor_sync(0xffffffffu, s0, 4);
    s1 += __shfl_xor_sync(0xffffffffu, s1, 4);

    float g0 = 0.0f, g1 = 0.0f;
    if (m == 0) {
        float inv_beta = 1.0f / tmpp[0];
        float bb = b2[0];
        float x0 = (__logf(nz0) - __logf(1.0f - nz0) + s0 + bb) * inv_beta;
        float x1 = (__logf(nz1) - __logf(1.0f - nz1) + s1 + bb) * inv_beta;
        g0 = 1.0f / (1.0f + __expf(-x0));
        g1 = 1.0f / (1.0f + __expf(-x1));
    }
    // combine the two directions of each edge: grp0<->grp1 (xor 8)
    float go0 = __shfl_xor_sync(0xffffffffu, g0, 8);
    float go1 = __shfl_xor_sync(0xffffffffu, g1, 8);
    if ((lane & 15) == 0) {       // lane 0 (el=0), lane 16 (el=1)
        int e0 = base + el;
        int e1 = base + 2 + el;
        if (e0 < E) out[e0] = 0.5f * (g0 + go0);
        if (e1 < E) out[e1] = 0.5f * (g1 + go1);
    }
}

// ---------------------------------------------------------------------------
extern "C" void kernel_launch(void* const* d_in, const int* in_sizes, int n_in,
                              void* d_out, int out_size)
{
    const float* embed = (const float*)d_in[0];
    const void*  ei    = d_in[1];
    const float* noise = (const float*)d_in[2];
    const float* tmp   = (const float*)d_in[3];
    const float* W1    = (const float*)d_in[4];
    const float* b1    = (const float*)d_in[5];
    const float* W2    = (const float*)d_in[6];
    const float* b2    = (const float*)d_in[7];
    float*       out   = (float*)d_out;

    int N = in_sizes[0] / 64;      // 1500
    int E = in_sizes[1] / 2;       // 65536

    precompute_h<<<(N + 15) / 16, 256>>>(embed, W1, b1, N);

    // 4 edges per warp, 8 warps per block -> 32 edges per block
    int blocks = (E + 31) / 32;
    edge_gate<<<blocks, 256>>>(ei, noise, tmp, W2, b2, out, N, E);
}

// round 12
// speedup vs baseline: 1.7500x; 1.0672x over previous
#include <cuda_runtime.h>
#include <cuda_fp16.h>

// Inputs (metadata order):
//  0 embed  [N,64] f32          (N=1500)
//  1 edge_index [2,E]           (E=65536; int32 OR int64, per-warp sniffed)
//  2 noise  [N*N] f32
//  3 tmp    [1] f32
//  4 W1     [128,64] f32
//  5 b1     [64] f32
//  6 W2     [64,1] f32
//  7 b2     [1] f32
// Output: edge_mask [E] f32

#define MAXN 1500

// Per node n, row of 128 halfs: [0:64) = h1[n]+b1, [64:128) = h2[n]  (384 KB)
__device__ __align__(256) __half g_h16[MAXN * 128];

// ---------------------------------------------------------------------------
// Kernel 1: h table (fp16). 16 nodes per block, 2 nodes per thread.
// ---------------------------------------------------------------------------
__global__ void __launch_bounds__(256) precompute_h(
    const float* __restrict__ embed,
    const float* __restrict__ W1,
    const float* __restrict__ b1,
    int N)
{
    __shared__ float se[16 * 64];
    int t  = threadIdx.x;
    int n0 = blockIdx.x * 16;

#pragma unroll
    for (int idx = t; idx < 1024; idx += 256) {
        int nl = idx >> 6, f = idx & 63;
        se[idx] = (n0 + nl < N) ? embed[(n0 + nl) * 64 + f] : 0.0f;
    }
    __syncthreads();

    int slot = t & 31;            // which (half, k-quad)
    int half = slot >> 4;         // 0 -> h1, 1 -> h2
    int k0   = (slot & 15) * 4;   // 4 adjacent k
    int grp  = t >> 5;            // 0..7 -> nodes grp and grp+8

    const float* e0 = se + grp * 64;
    const float* e1 = se + (grp + 8) * 64;

    float4 s0 = make_float4(0.f, 0.f, 0.f, 0.f);
    float4 s1 = make_float4(0.f, 0.f, 0.f, 0.f);
#pragma unroll
    for (int f = 0; f < 64; f++) {
        float4 w = *(const float4*)&W1[(half * 64 + f) * 64 + k0];
        float a = e0[f], b = e1[f];
        s0.x = fmaf(a, w.x, s0.x); s0.y = fmaf(a, w.y, s0.y);
        s0.z = fmaf(a, w.z, s0.z); s0.w = fmaf(a, w.w, s0.w);
        s1.x = fmaf(b, w.x, s1.x); s1.y = fmaf(b, w.y, s1.y);
        s1.z = fmaf(b, w.z, s1.z); s1.w = fmaf(b, w.w, s1.w);
    }
    if (half == 0) {
        float4 bb = *(const float4*)&b1[k0];
        s0.x += bb.x; s0.y += bb.y; s0.z += bb.z; s0.w += bb.w;
        s1.x += bb.x; s1.y += bb.y; s1.z += bb.z; s1.w += bb.w;
    }

    int node0 = n0 + grp, node1 = n0 + grp + 8;
    if (node0 < N) {
        __half2 lo = __floats2half2_rn(s0.x, s0.y);
        __half2 hi = __floats2half2_rn(s0.z, s0.w);
        uint2 p; p.x = *(unsigned*)&lo; p.y = *(unsigned*)&hi;
        *(uint2*)&g_h16[node0 * 128 + half * 64 + k0] = p;
    }
    if (node1 < N) {
        __half2 lo = __floats2half2_rn(s1.x, s1.y);
        __half2 hi = __floats2half2_rn(s1.z, s1.w);
        uint2 p; p.x = *(unsigned*)&lo; p.y = *(unsigned*)&hi;
        *(uint2*)&g_h16[node1 * 128 + half * 64 + k0] = p;
    }
}

// 8 halfs (one uint4 of fp16 h) -> relu(a+c) dot W2[8]
__device__ __forceinline__ float dot8(uint4 a, uint4 c, float4 wa, float4 wb)
{
    const __half2* ah = (const __half2*)&a;
    const __half2* ch = (const __half2*)&c;
    const __half2  z  = __float2half2_rn(0.0f);
    float2 f0 = __half22float2(__hmax2(__hadd2(ah[0], ch[0]), z));
    float2 f1 = __half22float2(__hmax2(__hadd2(ah[1], ch[1]), z));
    float2 f2 = __half22float2(__hmax2(__hadd2(ah[2], ch[2]), z));
    float2 f3 = __half22float2(__hmax2(__hadd2(ah[3], ch[3]), z));
    float s = f0.x * wa.x;
    s = fmaf(f0.y, wa.y, s);
    s = fmaf(f1.x, wa.z, s);
    s = fmaf(f1.y, wa.w, s);
    s = fmaf(f2.x, wb.x, s);
    s = fmaf(f2.y, wb.y, s);
    s = fmaf(f3.x, wb.z, s);
    s = fmaf(f3.y, wb.w, s);
    return s;
}

// ---------------------------------------------------------------------------
// Kernel 2: 8 edges per warp = 4 software-pipelined batches of the
// 8-lanes-per-row layout. All loads (dual-dtype index words in one divergent
// LDG, 4 noise loads, 8 h-row LDG.128s) issue before any consumption ->
// 4 independent compute chains per warp.
//   grp = lane>>3 (direction 0..3 of a batch), m = lane&7 (8 k's),
//   el = grp>>1 (edge-in-batch), top = grp&1.
// ---------------------------------------------------------------------------
__global__ void __launch_bounds__(256) edge_gate(
    const void* __restrict__ ei_raw,
    const float* __restrict__ noise,
    const float* __restrict__ tmpp,
    const float* __restrict__ W2,
    const float* __restrict__ b2,
    float* __restrict__ out,
    int N, int E)
{
    int tid   = threadIdx.x;
    int lane  = tid & 31;
    int gwarp = (blockIdx.x * blockDim.x + tid) >> 5;
    int base  = gwarp * 8;            // 8 edges per warp

    int grp = lane >> 3;              // direction 0..3 (within a batch)
    int m   = lane & 7;               // eighth of the 64-dot
    int el  = grp >> 1;               // edge-in-batch 0..1
    int top = grp & 1;                // 0: (i,j), 1: (j,i)

    const int* w32 = (const int*)ei_raw;

    // Index words, both dtype interpretations, one divergent LDG:
    //  lanes  0-7 : int32 src, edges base..base+7
    //  lanes  8-15: int32 dst
    //  lanes 16-23: int64-low src     lanes 24-31: int64-low dst
    int q  = lane & 7;
    int eq = min(base + q, E - 1);
    int v;
    if (lane < 8)        v = w32[eq];
    else if (lane < 16)  v = w32[E + eq];
    else if (lane < 24)  v = w32[2 * eq];
    else                 v = w32[2 * E + 2 * eq];

    // sniff: odd (high) words of 4 edges' src under the int64 reading
    int sn = 0;
    if (lane < 4) sn = w32[2 * min(base + lane, E - 1) + 1];
    bool is64 = (__ballot_sync(0xffffffffu, sn != 0) == 0u);
    int sb_src = is64 ? 16 : 0;
    int sb_dst = is64 ? 24 : 8;

    // decode all 8 node pairs (batch b edge: base + 2b + el)
    int iv[4], jv[4];
#pragma unroll
    for (int b = 0; b < 4; b++) {
        int sl = 2 * b + el;
        int ib = __shfl_sync(0xffffffffu, v, sb_src + sl);
        int jb = __shfl_sync(0xffffffffu, v, sb_dst + sl);
        iv[b] = min(max(ib, 0), N - 1);
        jv[b] = min(max(jb, 0), N - 1);
    }

    // scattered noise loads (m==0 lanes: 4 lanes x 4 batches, independent)
    float nz[4] = {0.f, 0.f, 0.f, 0.f};
    if (m == 0) {
#pragma unroll
        for (int b = 0; b < 4; b++)
            nz[b] = __ldg(noise + (top ? (jv[b] * N + iv[b])
                                       : (iv[b] * N + jv[b])));
    }

    // h rows for all 4 batches: 8 independent LDG.128
    uint4 a[4], c[4];
#pragma unroll
    for (int b = 0; b < 4; b++) {
        a[b] = __ldg((const uint4*)(g_h16 + (top ? jv[b] : iv[b]) * 128) + m);
        c[b] = __ldg((const uint4*)(g_h16 + (top ? iv[b] : jv[b]) * 128) + 8 + m);
    }

    const float4* W = (const float4*)W2 + 2 * m;
    float4 wa = W[0], wb = W[1];

    float s[4];
#pragma unroll
    for (int b = 0; b < 4; b++)
        s[b] = dot8(a[b], c[b], wa, wb);

    // interleaved reduces: 4 independent chains per level
#pragma unroll
    for (int off = 1; off <= 4; off <<= 1) {
#pragma unroll
        for (int b = 0; b < 4; b++)
            s[b] += __shfl_xor_sync(0xffffffffu, s[b], off);
    }

    float g[4] = {0.f, 0.f, 0.f, 0.f};
    if (m == 0) {
        float inv_beta = 1.0f / tmpp[0];
        float bb = b2[0];
#pragma unroll
        for (int b = 0; b < 4; b++) {
            float x = (__logf(nz[b]) - __logf(1.0f - nz[b]) + s[b] + bb) * inv_beta;
            g[b] = 1.0f / (1.0f + __expf(-x));
        }
    }
    // combine the two directions of each edge: grp<->grp^1 (xor 8)
#pragma unroll
    for (int b = 0; b < 4; b++) {
        float go = __shfl_xor_sync(0xffffffffu, g[b], 8);
        int e = base + 2 * b + el;
        if ((lane & 15) == 0 && e < E)
            out[e] = 0.5f * (g[b] + go);
    }
}

// ---------------------------------------------------------------------------
extern "C" void kernel_launch(void* const* d_in, const int* in_sizes, int n_in,
                              void* d_out, int out_size)
{
    const float* embed = (const float*)d_in[0];
    const void*  ei    = d_in[1];
    const float* noise = (const float*)d_in[2];
    const float* tmp   = (const float*)d_in[3];
    const float* W1    = (const float*)d_in[4];
    const float* b1    = (const float*)d_in[5];
    const float* W2    = (const float*)d_in[6];
    const float* b2    = (const float*)d_in[7];
    float*       out   = (float*)d_out;

    int N = in_sizes[0] / 64;      // 1500
    int E = in_sizes[1] / 2;       // 65536

    precompute_h<<<(N + 15) / 16, 256>>>(embed, W1, b1, N);

    // 8 edges per warp, 8 warps per block -> 64 edges per block
    int blocks = (E + 63) / 64;
    edge_gate<<<blocks, 256>>>(ei, noise, tmp, W2, b2, out, N, E);
}